// round 16
// baseline (speedup 1.0000x reference)
#include <cuda_runtime.h>

#define NU_F 0.5f
#define HH 1024
#define WW 1024
#define ROWS 4             // output rows per tile
#define TPB 256            // threads per block; TPB*4 == WW
#define YBLKS (HH / ROWS)  // 256 y-tiles per batch image
#define GRID_CTAS 912      // 152 SMs * 6 CTAs/SM resident on GB300

__device__ unsigned g_ticket;

__global__ void AI4Burgers_ticket_reset() { g_ticket = 0u; }

__global__ __launch_bounds__(TPB, 6)   // cap regs at 42 -> keep 6 CTAs/SM
void AI4Burgers_38096359915612_kernel(const float* __restrict__ u,
                                      const float* __restrict__ uvel,
                                      const float* __restrict__ w1,
                                      const float* __restrict__ w2,
                                      const float* __restrict__ w3,
                                      float* __restrict__ out,
                                      unsigned ntiles)
{
    __shared__ float swA[9];   // NU * w1
    __shared__ float swB[9];   // w2 + w3
    __shared__ unsigned s_tile;
    const int tx = threadIdx.x;
    if (tx < 9) {
        swA[tx] = NU_F * __ldg(&w1[tx]);
        swB[tx] = __ldg(&w2[tx]) + __ldg(&w3[tx]);
    }
    __syncthreads();

    float A[9], Bw[9];
#pragma unroll
    for (int i = 0; i < 9; i++) { A[i] = swA[i]; Bw[i] = swB[i]; }

    const int lane = tx & 31;
    const unsigned x0 = (unsigned)tx << 2;     // 4 outputs per thread in x
    const bool leftEdge  = (x0 == 0);
    const bool rightEdge = (x0 + 4 >= WW);

    // Persistent loop: dynamically ticketed tiles. Ticket order is y-major,
    // so concurrent CTAs work on y-adjacent tiles -> u halo rows hit L2.
    for (;;) {
        if (tx == 0) s_tile = atomicAdd(&g_ticket, 1u);
        __syncthreads();
        const unsigned tile = s_tile;
        __syncthreads();          // protect s_tile before next iteration's write
        if (tile >= ntiles) break;

        const unsigned y_blk = tile & (YBLKS - 1);   // tile % 256
        const unsigned z     = tile >> 8;            // tile / 256
        const unsigned y0 = y_blk * ROWS;
        const unsigned base = z * (unsigned)(HH * WW);
        const float* __restrict__ up = u + base;
        const float* __restrict__ vp = uvel + base;
        float* __restrict__ op = out + base;

        // rolling 3-row window; 6-wide per row:
        // r[0] <-> x0-1 (clamped), r[1..4] <-> x0..x0+3, r[5] <-> x0+4 (clamped)
        float r0[6], r1[6], r2[6];

#define LOAD_ROW(dst, gy)                                                   \
    do {                                                                    \
        const float* __restrict__ row_ = up + (unsigned)(gy) * WW;          \
        float4 v_ = *reinterpret_cast<const float4*>(row_ + x0);            \
        float lft_ = __shfl_up_sync(0xffffffffu, v_.w, 1);                  \
        float rgt_ = __shfl_down_sync(0xffffffffu, v_.x, 1);                \
        if (lane == 0)  lft_ = leftEdge  ? v_.x : __ldg(row_ + x0 - 1);     \
        if (lane == 31) rgt_ = rightEdge ? v_.w : __ldg(row_ + x0 + 4);     \
        (dst)[0] = lft_;                                                    \
        (dst)[1] = v_.x; (dst)[2] = v_.y; (dst)[3] = v_.z; (dst)[4] = v_.w; \
        (dst)[5] = rgt_;                                                    \
    } while (0)

        const int gym1 = (y0 == 0) ? 0 : (int)y0 - 1;
        LOAD_ROW(r0, gym1);
        LOAD_ROW(r1, y0);

#pragma unroll
        for (int j = 0; j < ROWS; j++) {
            const unsigned y = y0 + (unsigned)j;
            const unsigned gyp = (y + 1 < HH) ? (y + 1) : (HH - 1);
            LOAD_ROW(r2, gyp);

            // uvel: read-once stream -> evict-first
            float4 uvv = __ldcs(reinterpret_cast<const float4*>(vp + y * WW + x0));
            const float uva[4] = {uvv.x, uvv.y, uvv.z, uvv.w};

            float o[4];
#pragma unroll
            for (int i = 0; i < 4; i++) {
                float s1 = A[0] * r0[i];
                s1 = fmaf(A[1], r0[i + 1], s1);
                s1 = fmaf(A[2], r0[i + 2], s1);
                s1 = fmaf(A[3], r1[i],     s1);
                s1 = fmaf(A[4], r1[i + 1], s1);
                s1 = fmaf(A[5], r1[i + 2], s1);
                s1 = fmaf(A[6], r2[i],     s1);
                s1 = fmaf(A[7], r2[i + 1], s1);
                s1 = fmaf(A[8], r2[i + 2], s1);

                float s2 = Bw[0] * r0[i];
                s2 = fmaf(Bw[1], r0[i + 1], s2);
                s2 = fmaf(Bw[2], r0[i + 2], s2);
                s2 = fmaf(Bw[3], r1[i],     s2);
                s2 = fmaf(Bw[4], r1[i + 1], s2);
                s2 = fmaf(Bw[5], r1[i + 2], s2);
                s2 = fmaf(Bw[6], r2[i],     s2);
                s2 = fmaf(Bw[7], r2[i + 1], s2);
                s2 = fmaf(Bw[8], r2[i + 2], s2);

                // Lu = NU*conv1 - uvel*(conv2+conv3)  (NU folded into A)
                o[i] = fmaf(-uva[i], s2, s1);
            }

            float4 ov;
            ov.x = o[0]; ov.y = o[1]; ov.z = o[2]; ov.w = o[3];
            // out: write-once stream -> evict-first store
            __stcs(reinterpret_cast<float4*>(op + y * WW + x0), ov);

#pragma unroll
            for (int k = 0; k < 6; k++) { r0[k] = r1[k]; r1[k] = r2[k]; }
        }
#undef LOAD_ROW
    }
}

extern "C" void kernel_launch(void* const* d_in, const int* in_sizes, int n_in,
                              void* d_out, int out_size)
{
    const float* u    = (const float*)d_in[0];
    const float* uvel = (const float*)d_in[1];
    const float* w1   = (const float*)d_in[2];
    const float* w2   = (const float*)d_in[3];
    const float* w3   = (const float*)d_in[4];
    float* out = (float*)d_out;

    const int B = in_sizes[0] / (HH * WW);        // 16
    const unsigned ntiles = (unsigned)(B * YBLKS); // 4096

    AI4Burgers_ticket_reset<<<1, 1>>>();

    const unsigned grid = (ntiles < GRID_CTAS) ? ntiles : GRID_CTAS;
    AI4Burgers_38096359915612_kernel<<<grid, TPB>>>(u, uvel, w1, w2, w3, out, ntiles);
}

// round 17
// speedup vs baseline: 1.0993x; 1.0993x over previous
#include <cuda_runtime.h>

#define NU_F 0.5f
#define HH 1024
#define WW 1024
#define ROWS 4             // output rows per tile
#define TPB 256            // threads per block; TPB*4 == WW
#define YBLKS (HH / ROWS)  // 256 y-tiles per batch image
#define GRID_CTAS 912      // 152 SMs * 6 CTAs/SM resident on GB300

__global__ __launch_bounds__(TPB)
void AI4Burgers_38096359915612_kernel(const float* __restrict__ u,
                                      const float* __restrict__ uvel,
                                      const float* __restrict__ w1,
                                      const float* __restrict__ w2,
                                      const float* __restrict__ w3,
                                      float* __restrict__ out,
                                      unsigned ntiles)
{
    __shared__ float swA[9];   // NU * w1
    __shared__ float swB[9];   // w2 + w3
    const int tx = threadIdx.x;
    if (tx < 9) {
        swA[tx] = NU_F * __ldg(&w1[tx]);
        swB[tx] = __ldg(&w2[tx]) + __ldg(&w3[tx]);
    }
    __syncthreads();

    float A[9], Bw[9];
#pragma unroll
    for (int i = 0; i < 9; i++) { A[i] = swA[i]; Bw[i] = swB[i]; }

    const int lane = tx & 31;
    const unsigned x0 = (unsigned)tx << 2;     // 4 outputs per thread in x
    const bool leftEdge  = (x0 == 0);
    const bool rightEdge = (x0 + 4 >= WW);

    // Grid-stride persistent loop: no atomics, no in-loop barriers.
    // At step k all resident CTAs process a contiguous y-major tile range,
    // preserving L2 halo adjacency; next-tile loads issue right behind the
    // current tile's stores (no pipeline bubble).
    for (unsigned tile = blockIdx.x; tile < ntiles; tile += gridDim.x) {
        const unsigned y_blk = tile & (YBLKS - 1);   // tile % 256
        const unsigned z     = tile >> 8;            // tile / 256
        const unsigned y0 = y_blk * ROWS;
        const unsigned base = z * (unsigned)(HH * WW);
        const float* __restrict__ up = u + base;
        const float* __restrict__ vp = uvel + base;
        float* __restrict__ op = out + base;

        // rolling 3-row window; 6-wide per row:
        // r[0] <-> x0-1 (clamped), r[1..4] <-> x0..x0+3, r[5] <-> x0+4 (clamped)
        float r0[6], r1[6], r2[6];

#define LOAD_ROW(dst, gy)                                                   \
    do {                                                                    \
        const float* __restrict__ row_ = up + (unsigned)(gy) * WW;          \
        float4 v_ = *reinterpret_cast<const float4*>(row_ + x0);            \
        float lft_ = __shfl_up_sync(0xffffffffu, v_.w, 1);                  \
        float rgt_ = __shfl_down_sync(0xffffffffu, v_.x, 1);                \
        if (lane == 0)  lft_ = leftEdge  ? v_.x : __ldg(row_ + x0 - 1);     \
        if (lane == 31) rgt_ = rightEdge ? v_.w : __ldg(row_ + x0 + 4);     \
        (dst)[0] = lft_;                                                    \
        (dst)[1] = v_.x; (dst)[2] = v_.y; (dst)[3] = v_.z; (dst)[4] = v_.w; \
        (dst)[5] = rgt_;                                                    \
    } while (0)

        const int gym1 = (y0 == 0) ? 0 : (int)y0 - 1;
        LOAD_ROW(r0, gym1);
        LOAD_ROW(r1, y0);

#pragma unroll
        for (int j = 0; j < ROWS; j++) {
            const unsigned y = y0 + (unsigned)j;
            const unsigned gyp = (y + 1 < HH) ? (y + 1) : (HH - 1);
            LOAD_ROW(r2, gyp);

            // uvel: read-once stream -> evict-first
            float4 uvv = __ldcs(reinterpret_cast<const float4*>(vp + y * WW + x0));
            const float uva[4] = {uvv.x, uvv.y, uvv.z, uvv.w};

            float o[4];
#pragma unroll
            for (int i = 0; i < 4; i++) {
                float s1 = A[0] * r0[i];
                s1 = fmaf(A[1], r0[i + 1], s1);
                s1 = fmaf(A[2], r0[i + 2], s1);
                s1 = fmaf(A[3], r1[i],     s1);
                s1 = fmaf(A[4], r1[i + 1], s1);
                s1 = fmaf(A[5], r1[i + 2], s1);
                s1 = fmaf(A[6], r2[i],     s1);
                s1 = fmaf(A[7], r2[i + 1], s1);
                s1 = fmaf(A[8], r2[i + 2], s1);

                float s2 = Bw[0] * r0[i];
                s2 = fmaf(Bw[1], r0[i + 1], s2);
                s2 = fmaf(Bw[2], r0[i + 2], s2);
                s2 = fmaf(Bw[3], r1[i],     s2);
                s2 = fmaf(Bw[4], r1[i + 1], s2);
                s2 = fmaf(Bw[5], r1[i + 2], s2);
                s2 = fmaf(Bw[6], r2[i],     s2);
                s2 = fmaf(Bw[7], r2[i + 1], s2);
                s2 = fmaf(Bw[8], r2[i + 2], s2);

                // Lu = NU*conv1 - uvel*(conv2+conv3)  (NU folded into A)
                o[i] = fmaf(-uva[i], s2, s1);
            }

            float4 ov;
            ov.x = o[0]; ov.y = o[1]; ov.z = o[2]; ov.w = o[3];
            // out: write-once stream -> evict-first store
            __stcs(reinterpret_cast<float4*>(op + y * WW + x0), ov);

#pragma unroll
            for (int k = 0; k < 6; k++) { r0[k] = r1[k]; r1[k] = r2[k]; }
        }
#undef LOAD_ROW
    }
}

extern "C" void kernel_launch(void* const* d_in, const int* in_sizes, int n_in,
                              void* d_out, int out_size)
{
    const float* u    = (const float*)d_in[0];
    const float* uvel = (const float*)d_in[1];
    const float* w1   = (const float*)d_in[2];
    const float* w2   = (const float*)d_in[3];
    const float* w3   = (const float*)d_in[4];
    float* out = (float*)d_out;

    const int B = in_sizes[0] / (HH * WW);         // 16
    const unsigned ntiles = (unsigned)(B * YBLKS); // 4096

    const unsigned grid = (ntiles < GRID_CTAS) ? ntiles : GRID_CTAS;
    AI4Burgers_38096359915612_kernel<<<grid, TPB>>>(u, uvel, w1, w2, w3, out, ntiles);
}